// round 13
// baseline (speedup 1.0000x reference)
#include <cuda_runtime.h>
#include <cuda_bf16.h>

// ---------------- problem constants ----------------
#define BB 4
#define AA 10
#define LL 4096
#define NPROP (LL * AA)          // 40960 per batch (fits in 16 bits)
#define TOTAL (BB * NPROP)       // 163840
#define PRE_NMS 6000
#define POST_NMS 300
#define NCHUNK ((PRE_NMS + 31) / 32)   // 188
#define NMS_THRESH_F 0.7f
#define MIN_SIZE_F 8.0f
#define FEAT_STRIDE 8
#define CLIP_MAX 32767.0f        // L*FEAT_STRIDE - 1
#define FULLMASK 0xFFFFFFFFu

#define MEGA_THREADS 1024
#define MEGA_WARPS 32
#define NHBINS 8192              // 13-bit histogram
#define SEL_CAP 8192             // selected-candidate capacity (power of 2 for bitonic)

// ---------------- static device scratch (no allocations allowed) ----------------
__device__ float2   g_box[TOTAL];   // decoded boxes, reference index order
__device__ unsigned g_dkey[TOTAL];  // descending-orderable score key (small = high score)

__constant__ float c_scales[AA] = {2.f, 4.f, 5.f, 6.f, 8.f, 9.f, 10.f, 12.f, 14.f, 16.f};

// ---------------- kernel 1: decode proposals + score keys (coalesced loads) ----------
__global__ void compute_props(const float* __restrict__ scores_in,
                              const float* __restrict__ deltas_in) {
    int t = blockIdx.x * blockDim.x + threadIdx.x;
    if (t >= TOTAL) return;
    int l = t & (LL - 1);
    int ba = t >> 12;                  // b*AA + a
    int b = ba / AA;
    int a = ba - b * AA;

    const int base = b * (2 * AA) * LL;
    float score = scores_in[base + (AA + a) * LL + l];
    float d0    = deltas_in[base + (2 * a) * LL + l];
    float d1    = deltas_in[base + (2 * a + 1) * LL + l];

    float ws   = c_scales[a] * (float)FEAT_STRIDE;
    float ctrA = ((float)FEAT_STRIDE - 1.0f) * 0.5f;      // 3.5
    float shift = (float)(l * FEAT_STRIDE);
    float x1a = ctrA - 0.5f * (ws - 1.0f) + shift;
    float x2a = ctrA + 0.5f * (ws - 1.0f) + shift;

    float width = x2a - x1a + 1.0f;
    float ctr   = x1a + 0.5f * width;

    float pred_ctr = d0 * width + ctr;
    float pred_l   = expf(d1) * width;

    float x1 = pred_ctr - 0.5f * pred_l;
    float x2 = pred_ctr + 0.5f * pred_l;
    x1 = fminf(fmaxf(x1, 0.0f), CLIP_MAX);
    x2 = fminf(fmaxf(x2, 0.0f), CLIP_MAX);

    float ls = x2 - x1 + 1.0f;
    if (ls < MIN_SIZE_F) score = 0.0f;

    int r = l * AA + a;                // reference proposal index within batch
    int idx = b * NPROP + r;
    g_box[idx] = make_float2(x1, x2);

    // ascending-orderable then invert: small dkey = high score
    unsigned u = __float_as_uint(score);
    unsigned asc = (u & 0x80000000u) ? ~u : (u | 0x80000000u);
    g_dkey[idx] = ~asc;
}

// ---------------- kernel 2: mega — select + bitonic sort + greedy NMS (1 block/batch)
// dynamic smem: s_sort[SEL_CAP] u64 (64K) + sboxes[PRE_NMS] float2 (48000) +
//               skept[POST_NMS] float4 (4800)
__global__ void __launch_bounds__(MEGA_THREADS)
mega_kernel(float* __restrict__ out) {
    extern __shared__ unsigned char raw[];
    unsigned long long* s_sort = (unsigned long long*)raw;
    float2* sboxes = (float2*)(s_sort + SEL_CAP);
    float4* skept  = (float4*)(sboxes + PRE_NMS);
    __shared__ unsigned s_hist[NHBINS];          // 32 KB
    __shared__ unsigned s_part[MEGA_THREADS];    // 4 KB
    __shared__ unsigned s_sup[MEGA_WARPS];
    __shared__ unsigned s_rowp[MEGA_WARPS][32];
    __shared__ unsigned s_T, s_cnt;
    __shared__ int s_K;

    const int b    = blockIdx.x;
    const int tid  = threadIdx.x;
    const int wid  = tid >> 5;
    const int lane = tid & 31;

    for (int i = tid; i < NHBINS; i += MEGA_THREADS) s_hist[i] = 0;
    for (int i = tid; i < POST_NMS; i += MEGA_THREADS) {
        float* o = out + (b * POST_NMS + i) * 3;
        o[0] = (float)b; o[1] = 0.0f; o[2] = 0.0f;
    }
    if (tid == 0) { s_cnt = 0; s_K = 0; }
    __syncthreads();

    const unsigned* __restrict__ dk = g_dkey + b * NPROP;

    // ---- histogram of top 13 key bits ----
    for (int i = tid; i < NPROP; i += MEGA_THREADS)
        atomicAdd(&s_hist[dk[i] >> 19], 1u);
    __syncthreads();

    // ---- scan: find threshold bin T (cumulative from bin 0 reaches PRE_NMS) ----
    {
        const int base = tid * (NHBINS / MEGA_THREADS);   // 8 bins per thread
        unsigned own = 0;
        #pragma unroll
        for (int k = 0; k < NHBINS / MEGA_THREADS; ++k) own += s_hist[base + k];
        s_part[tid] = own;
        __syncthreads();
        for (int off = 1; off < MEGA_THREADS; off <<= 1) {
            unsigned v = (tid >= off) ? s_part[tid - off] : 0u;
            __syncthreads();
            s_part[tid] += v;
            __syncthreads();
        }
        unsigned incl = s_part[tid];
        unsigned before = incl - own;
        if (before < PRE_NMS && incl >= PRE_NMS) {   // crossing inside this thread
            unsigned cum = before;
            #pragma unroll
            for (int k = 0; k < NHBINS / MEGA_THREADS; ++k) {
                cum += s_hist[base + k];
                if (cum >= PRE_NMS) { s_T = (unsigned)(base + k); break; }
            }
        }
        __syncthreads();
    }
    const unsigned T = s_T;

    // ---- extract selected candidates (full 48-bit order key, position-independent) ----
    for (int i = tid; i < NPROP; i += MEGA_THREADS) {
        unsigned d = dk[i];
        if ((d >> 19) <= T) {
            unsigned slot = atomicAdd(&s_cnt, 1u);
            if (slot < SEL_CAP)
                s_sort[slot] = ((unsigned long long)d << 16) | (unsigned)i;
        }
    }
    __syncthreads();
    const unsigned C = s_cnt;
    for (int i = tid; i < SEL_CAP; i += MEGA_THREADS)
        if ((unsigned)i >= C) s_sort[i] = ~0ULL;
    __syncthreads();

    // ---- bitonic sort ascending: (dkey asc = score desc, then r asc) ----
    for (int k = 2; k <= SEL_CAP; k <<= 1) {
        for (int j = k >> 1; j > 0; j >>= 1) {
            for (int i = tid; i < SEL_CAP; i += MEGA_THREADS) {
                int ixj = i ^ j;
                if (ixj > i) {
                    unsigned long long a = s_sort[i];
                    unsigned long long c = s_sort[ixj];
                    bool up = ((i & k) == 0);
                    if ((a > c) == up) { s_sort[i] = c; s_sort[ixj] = a; }
                }
            }
            __syncthreads();
        }
    }

    // ---- gather top-PRE_NMS boxes ----
    for (int i = tid; i < PRE_NMS; i += MEGA_THREADS) {
        int r = (int)(s_sort[i] & 0xFFFFu);
        sboxes[i] = g_box[b * NPROP + r];
    }
    __syncthreads();

    // ---- chunked greedy NMS (R11 structure, 32 warps) ----
    for (int c = 0; c < NCHUNK; ++c) {
        const int i = c * 32 + lane;
        const bool valid = (i < PRE_NMS);
        const int nvalid = PRE_NMS - c * 32;
        const unsigned validMask =
            (nvalid >= 32) ? FULLMASK : ((1u << nvalid) - 1u);

        float x1 = 0.0f, x2 = -2.0f;
        if (valid) { float2 t0 = sboxes[i]; x1 = t0.x; x2 = t0.y; }
        const float len = x2 - x1 + 1.0f;
        const int K = s_K;

        // phase 1 (all 32 warps): candidate vs kept list, j strided by warp
        bool sup = !valid;
        int it = 0;
        for (int j = wid; j < K; j += MEGA_WARPS) {
            float4 kb = skept[j];                    // broadcast within warp
            float inter = fminf(x2, kb.y) - fmaxf(x1, kb.x) + 1.0f;
            float uni = len + kb.z - inter;
            if (inter > 0.6999f * uni) {             // prefilter; decision by division
                if (inter / uni > NMS_THRESH_F) sup = true;
            }
            if (((++it) & 3) == 0 && __all_sync(FULLMASK, sup)) break;
        }
        {
            unsigned bal = __ballot_sync(FULLMASK, sup);
            if (lane == 0) s_sup[wid] = bal;
        }

        // phase 2: warp w (1..31) handles butterfly offset d = w; warp 0 idle
        {
            unsigned rowp = 0u;
            if (wid > 0) {
                const int d = wid;
                float ox1 = __shfl_xor_sync(FULLMASK, x1, d);
                float ox2 = __shfl_xor_sync(FULLMASK, x2, d);
                float olen = ox2 - ox1 + 1.0f;
                float inter = fminf(x2, ox2) - fmaxf(x1, ox1) + 1.0f;
                float uni = len + olen - inter;
                if (inter > 0.6999f * uni) {
                    if (inter / uni > NMS_THRESH_F) rowp |= 1u << (lane ^ d);
                }
            }
            s_rowp[wid][lane] = rowp;
        }
        __syncthreads();

        // phases 3-4 (warp 0 only): resolve + append
        if (wid == 0) {
            unsigned removed = ~validMask;
            #pragma unroll
            for (int w = 0; w < MEGA_WARPS; ++w) removed |= s_sup[w];

            unsigned row = 0u;
            #pragma unroll
            for (int w = 0; w < MEGA_WARPS; ++w) row |= s_rowp[w][lane];
            row &= validMask;

            unsigned keptbits = 0u;
            unsigned alive = ~removed;
            while (alive) {
                int p = __ffs(alive) - 1;                       // uniform
                keptbits |= 1u << p;
                unsigned rowp = __shfl_sync(FULLMASK, row, p);
                removed |= rowp;
                alive = ~removed & ~((2u << p) - 1u);
            }

            int nk = __popc(keptbits);
            if (nk) {
                int myrank = K + __popc(keptbits & ((1u << lane) - 1u));
                if (((keptbits >> lane) & 1u) && myrank < POST_NMS) {
                    skept[myrank] = make_float4(x1, x2, len, 0.0f);
                    float* o = out + (b * POST_NMS + myrank) * 3;
                    o[1] = x1; o[2] = x2;
                }
                if (lane == 0) s_K = K + nk;
            }
        }
        __syncthreads();
        if (s_K >= POST_NMS) break;
    }
}

// ---------------- host launcher ----------------
extern "C" void kernel_launch(void* const* d_in, const int* in_sizes, int n_in,
                              void* d_out, int out_size) {
    (void)in_sizes; (void)n_in; (void)out_size;
    const float* scores = (const float*)d_in[0];
    const float* deltas = (const float*)d_in[1];
    float* out = (float*)d_out;

    compute_props<<<(TOTAL + 255) / 256, 256>>>(scores, deltas);

    const int smem_bytes = SEL_CAP * (int)sizeof(unsigned long long)
                         + PRE_NMS * (int)sizeof(float2)
                         + POST_NMS * (int)sizeof(float4);   // 117,136 B
    cudaFuncSetAttribute(mega_kernel, cudaFuncAttributeMaxDynamicSharedMemorySize, smem_bytes);
    mega_kernel<<<BB, MEGA_THREADS, smem_bytes>>>(out);
}

// round 14
// speedup vs baseline: 1.5623x; 1.5623x over previous
#include <cuda_runtime.h>
#include <cuda_bf16.h>
#include <cub/block/block_radix_sort.cuh>

// ---------------- problem constants ----------------
#define BB 4
#define AA 10
#define LL 4096
#define NPROP (LL * AA)          // 40960 per batch (fits in 16 bits)
#define TOTAL (BB * NPROP)       // 163840
#define PRE_NMS 6000
#define POST_NMS 300
#define NCHUNK ((PRE_NMS + 31) / 32)   // 188
#define NMS_THRESH_F 0.7f
#define MIN_SIZE_F 8.0f
#define FEAT_STRIDE 8
#define CLIP_MAX 32767.0f        // L*FEAT_STRIDE - 1
#define FULLMASK 0xFFFFFFFFu

#define MEGA_THREADS 1024
#define MEGA_WARPS 32
#define NHBINS 8192              // 13-bit histogram
#define SEL_CAP 8192             // selected-candidate capacity
#define ITEMS (SEL_CAP / MEGA_THREADS)   // 8 keys per thread

using BlockRadixSortT = cub::BlockRadixSort<unsigned long long, MEGA_THREADS, ITEMS>;

static constexpr size_t SORT_REGION =
    (sizeof(typename BlockRadixSortT::TempStorage) > (size_t)SEL_CAP * 8)
        ? ((sizeof(typename BlockRadixSortT::TempStorage) + 15) & ~(size_t)15)
        : (size_t)SEL_CAP * 8;

// ---------------- static device scratch (no allocations allowed) ----------------
__device__ float2   g_box[TOTAL];   // decoded boxes, reference index order
__device__ unsigned g_dkey[TOTAL];  // descending-orderable score key (small = high score)

__constant__ float c_scales[AA] = {2.f, 4.f, 5.f, 6.f, 8.f, 9.f, 10.f, 12.f, 14.f, 16.f};

// ---------------- kernel 1: decode proposals + score keys (coalesced loads) ----------
__global__ void compute_props(const float* __restrict__ scores_in,
                              const float* __restrict__ deltas_in) {
    int t = blockIdx.x * blockDim.x + threadIdx.x;
    if (t >= TOTAL) return;
    int l = t & (LL - 1);
    int ba = t >> 12;                  // b*AA + a
    int b = ba / AA;
    int a = ba - b * AA;

    const int base = b * (2 * AA) * LL;
    float score = scores_in[base + (AA + a) * LL + l];
    float d0    = deltas_in[base + (2 * a) * LL + l];
    float d1    = deltas_in[base + (2 * a + 1) * LL + l];

    float ws   = c_scales[a] * (float)FEAT_STRIDE;
    float ctrA = ((float)FEAT_STRIDE - 1.0f) * 0.5f;      // 3.5
    float shift = (float)(l * FEAT_STRIDE);
    float x1a = ctrA - 0.5f * (ws - 1.0f) + shift;
    float x2a = ctrA + 0.5f * (ws - 1.0f) + shift;

    float width = x2a - x1a + 1.0f;
    float ctr   = x1a + 0.5f * width;

    float pred_ctr = d0 * width + ctr;
    float pred_l   = expf(d1) * width;

    float x1 = pred_ctr - 0.5f * pred_l;
    float x2 = pred_ctr + 0.5f * pred_l;
    x1 = fminf(fmaxf(x1, 0.0f), CLIP_MAX);
    x2 = fminf(fmaxf(x2, 0.0f), CLIP_MAX);

    float ls = x2 - x1 + 1.0f;
    if (ls < MIN_SIZE_F) score = 0.0f;

    int r = l * AA + a;                // reference proposal index within batch
    int idx = b * NPROP + r;
    g_box[idx] = make_float2(x1, x2);

    // ascending-orderable then invert: small dkey = high score
    unsigned u = __float_as_uint(score);
    unsigned asc = (u & 0x80000000u) ? ~u : (u | 0x80000000u);
    g_dkey[idx] = ~asc;
}

// ---------------- kernel 2: mega — select + block radix sort + greedy NMS ------------
// dynamic smem: [SORT_REGION: extraction buffer, reused as radix temp storage]
//               [sboxes: PRE_NMS float2] [skept: POST_NMS float4]
__global__ void __launch_bounds__(MEGA_THREADS)
mega_kernel(float* __restrict__ out) {
    extern __shared__ unsigned char raw[];
    unsigned long long* s_sort = (unsigned long long*)raw;        // extraction buffer
    float2* sboxes = (float2*)(raw + SORT_REGION);
    float4* skept  = (float4*)(sboxes + PRE_NMS);
    __shared__ unsigned s_hist[NHBINS];          // 32 KB
    __shared__ unsigned s_part[MEGA_THREADS];    // 4 KB
    __shared__ unsigned s_sup[MEGA_WARPS];
    __shared__ unsigned s_rowp[MEGA_WARPS][32];
    __shared__ unsigned s_T, s_cnt;
    __shared__ int s_K;

    const int b    = blockIdx.x;
    const int tid  = threadIdx.x;
    const int wid  = tid >> 5;
    const int lane = tid & 31;

    for (int i = tid; i < NHBINS; i += MEGA_THREADS) s_hist[i] = 0;
    for (int i = tid; i < POST_NMS; i += MEGA_THREADS) {
        float* o = out + (b * POST_NMS + i) * 3;
        o[0] = (float)b; o[1] = 0.0f; o[2] = 0.0f;
    }
    if (tid == 0) { s_cnt = 0; s_K = 0; }
    __syncthreads();

    const unsigned* __restrict__ dk = g_dkey + b * NPROP;

    // ---- histogram of top 13 key bits ----
    for (int i = tid; i < NPROP; i += MEGA_THREADS)
        atomicAdd(&s_hist[dk[i] >> 19], 1u);
    __syncthreads();

    // ---- scan: find threshold bin T (cumulative from bin 0 reaches PRE_NMS) ----
    {
        const int base = tid * (NHBINS / MEGA_THREADS);   // 8 bins per thread
        unsigned own = 0;
        #pragma unroll
        for (int k = 0; k < NHBINS / MEGA_THREADS; ++k) own += s_hist[base + k];
        s_part[tid] = own;
        __syncthreads();
        for (int off = 1; off < MEGA_THREADS; off <<= 1) {
            unsigned v = (tid >= off) ? s_part[tid - off] : 0u;
            __syncthreads();
            s_part[tid] += v;
            __syncthreads();
        }
        unsigned incl = s_part[tid];
        unsigned before = incl - own;
        if (before < PRE_NMS && incl >= PRE_NMS) {   // crossing inside this thread
            unsigned cum = before;
            #pragma unroll
            for (int k = 0; k < NHBINS / MEGA_THREADS; ++k) {
                cum += s_hist[base + k];
                if (cum >= PRE_NMS) { s_T = (unsigned)(base + k); break; }
            }
        }
        __syncthreads();
    }
    const unsigned T = s_T;

    // ---- extract selected candidates (full 48-bit order key, position-independent) ----
    for (int i = tid; i < NPROP; i += MEGA_THREADS) {
        unsigned d = dk[i];
        if ((d >> 19) <= T) {
            unsigned slot = atomicAdd(&s_cnt, 1u);
            if (slot < SEL_CAP)
                s_sort[slot] = ((unsigned long long)d << 16) | (unsigned)i;
        }
    }
    __syncthreads();
    const unsigned C = s_cnt;
    for (int i = tid; i < SEL_CAP; i += MEGA_THREADS)
        if ((unsigned)i >= C) s_sort[i] = ~0ULL;
    __syncthreads();

    // ---- block radix sort (keys in registers; smem region reused as temp storage) ----
    {
        unsigned long long keys[ITEMS];
        #pragma unroll
        for (int k = 0; k < ITEMS; ++k) keys[k] = s_sort[tid * ITEMS + k];
        __syncthreads();   // extraction buffer dead; safe to alias as temp storage

        BlockRadixSortT(*reinterpret_cast<typename BlockRadixSortT::TempStorage*>(raw))
            .Sort(keys, 0, 48);
        __syncthreads();

        // blocked output: thread t holds global ranks t*ITEMS .. t*ITEMS+ITEMS-1
        #pragma unroll
        for (int k = 0; k < ITEMS; ++k) {
            int rank = tid * ITEMS + k;
            if (rank < PRE_NMS) {
                int r = (int)(keys[k] & 0xFFFFu);
                sboxes[rank] = g_box[b * NPROP + r];
            }
        }
    }
    __syncthreads();

    // ---- chunked greedy NMS (32 warps) ----
    for (int c = 0; c < NCHUNK; ++c) {
        const int i = c * 32 + lane;
        const bool valid = (i < PRE_NMS);
        const int nvalid = PRE_NMS - c * 32;
        const unsigned validMask =
            (nvalid >= 32) ? FULLMASK : ((1u << nvalid) - 1u);

        float x1 = 0.0f, x2 = -2.0f;
        if (valid) { float2 t0 = sboxes[i]; x1 = t0.x; x2 = t0.y; }
        const float len = x2 - x1 + 1.0f;
        const int K = s_K;

        // phase 1 (all 32 warps): candidate vs kept list, j strided by warp
        bool sup = !valid;
        int it = 0;
        for (int j = wid; j < K; j += MEGA_WARPS) {
            float4 kb = skept[j];                    // broadcast within warp
            float inter = fminf(x2, kb.y) - fmaxf(x1, kb.x) + 1.0f;
            float uni = len + kb.z - inter;
            if (inter > 0.6999f * uni) {             // prefilter; decision by division
                if (inter / uni > NMS_THRESH_F) sup = true;
            }
            if (((++it) & 3) == 0 && __all_sync(FULLMASK, sup)) break;
        }
        {
            unsigned bal = __ballot_sync(FULLMASK, sup);
            if (lane == 0) s_sup[wid] = bal;
        }

        // phase 2: warp w (1..31) handles butterfly offset d = w; warp 0 idle
        {
            unsigned rowp = 0u;
            if (wid > 0) {
                const int d = wid;
                float ox1 = __shfl_xor_sync(FULLMASK, x1, d);
                float ox2 = __shfl_xor_sync(FULLMASK, x2, d);
                float olen = ox2 - ox1 + 1.0f;
                float inter = fminf(x2, ox2) - fmaxf(x1, ox1) + 1.0f;
                float uni = len + olen - inter;
                if (inter > 0.6999f * uni) {
                    if (inter / uni > NMS_THRESH_F) rowp |= 1u << (lane ^ d);
                }
            }
            s_rowp[wid][lane] = rowp;
        }
        __syncthreads();

        // phases 3-4 (warp 0 only): resolve + append
        if (wid == 0) {
            unsigned removed = ~validMask;
            #pragma unroll
            for (int w = 0; w < MEGA_WARPS; ++w) removed |= s_sup[w];

            unsigned row = 0u;
            #pragma unroll
            for (int w = 0; w < MEGA_WARPS; ++w) row |= s_rowp[w][lane];
            row &= validMask;

            unsigned keptbits = 0u;
            unsigned alive = ~removed;
            while (alive) {
                int p = __ffs(alive) - 1;                       // uniform
                keptbits |= 1u << p;
                unsigned rowp = __shfl_sync(FULLMASK, row, p);
                removed |= rowp;
                alive = ~removed & ~((2u << p) - 1u);
            }

            int nk = __popc(keptbits);
            if (nk) {
                int myrank = K + __popc(keptbits & ((1u << lane) - 1u));
                if (((keptbits >> lane) & 1u) && myrank < POST_NMS) {
                    skept[myrank] = make_float4(x1, x2, len, 0.0f);
                    float* o = out + (b * POST_NMS + myrank) * 3;
                    o[1] = x1; o[2] = x2;
                }
                if (lane == 0) s_K = K + nk;
            }
        }
        __syncthreads();
        if (s_K >= POST_NMS) break;
    }
}

// ---------------- host launcher ----------------
extern "C" void kernel_launch(void* const* d_in, const int* in_sizes, int n_in,
                              void* d_out, int out_size) {
    (void)in_sizes; (void)n_in; (void)out_size;
    const float* scores = (const float*)d_in[0];
    const float* deltas = (const float*)d_in[1];
    float* out = (float*)d_out;

    compute_props<<<(TOTAL + 255) / 256, 256>>>(scores, deltas);

    const int smem_bytes = (int)SORT_REGION
                         + PRE_NMS * (int)sizeof(float2)
                         + POST_NMS * (int)sizeof(float4);
    cudaFuncSetAttribute(mega_kernel, cudaFuncAttributeMaxDynamicSharedMemorySize, smem_bytes);
    mega_kernel<<<BB, MEGA_THREADS, smem_bytes>>>(out);
}